// round 8
// baseline (speedup 1.0000x reference)
#include <cuda_runtime.h>
#include <cuda_fp16.h>

// ============================================================================
// RNN_35244501631277 — GB300 persistent recurrence, round 8
//
// R7 measured 1483us (predicted 1350-1500): tail-latency model CONFIRMED.
// Remaining per-phase: ~3.0us = ~1.6us L2 weight stream + ~1.4us serialized
// dependency chain (poll-all -> sync -> MAC -> reduce -> publish).
// This round pipelines the chain INTO the MAC:
//   - per-thread direct polling of exactly the 8 input words it needs
//     (no smem staging, no pre-MAC sync; straggler overlaps compute)
//   - parity double-buffered reduction scratch -> ONE __syncthreads/phase
//   - weight prefetch still issued the moment w[] dies
// Chain drops to ~0.5us; phase period -> stream floor (~1.7-2.0us).
// ============================================================================

#define H          2048
#define STEPS      119
#define NB         16384
#define CPC        64         // CTAs per chain
#define NCTAS      128
#define NTHREADS   1024
#define COLS       32
#define NPHASES    476

typedef unsigned long long ull;

__device__ __half g_wh[8][H * H];        // fp16 weights, CTA-sliced (32 cols)
__device__ ull    g_sp[2][H];            // p-state (epoch|value) words
__device__ ull    g_st[2][H];            // t-state words
__device__ ull    g_tabp[2][STEPS][H];   // step-table words
__device__ float  g_proj[2][STEPS];

#define ZERO_WORDS (2 * H + 2 * H + 2 * STEPS * H)

__device__ __forceinline__ float silu(float x) {
    return x / (1.0f + __expf(-x));
}

__device__ __forceinline__ ull ldpair(const ull* p) {
    ull v;
    asm volatile("ld.global.cg.b64 %0, [%1];" : "=l"(v) : "l"(p));
    return v;
}

__device__ __forceinline__ float poll_pair(const ull* p, unsigned expep) {
    ull v = ldpair(p);
    while ((unsigned)(v >> 32) != expep) {
        __nanosleep(32);
        v = ldpair(p);
    }
    return __uint_as_float((unsigned)v);
}

__device__ __forceinline__ void push_pair(ull* p, unsigned ep, float val) {
    ull v = ((ull)ep << 32) | (ull)__float_as_uint(val);
    asm volatile("st.global.cg.b64 [%0], %1;" :: "l"(p), "l"(v) : "memory");
}

extern "C" __global__ void zero_kernel() {
    int i = blockIdx.x * blockDim.x + threadIdx.x;
    if (i < 2 * H)           ((ull*)g_sp)[i] = 0;
    else if (i < 4 * H)      ((ull*)g_st)[i - 2 * H] = 0;
    else if (i < ZERO_WORDS) ((ull*)g_tabp)[i - 4 * H] = 0;
}

// fp32 -> fp16, CTA-sliced 32-col layout: dst[m][lc*H*32 + row*32 + co]
extern "C" __global__ void convert_kernel(const float* __restrict__ pW1,
                                          const float* __restrict__ pW2,
                                          const float* __restrict__ nW1,
                                          const float* __restrict__ nW2) {
    const int idx = blockIdx.x * blockDim.x + threadIdx.x;
    const int m   = idx >> 19;
    const int rem = idx & ((1 << 19) - 1);
    const int row = rem >> 8;
    const int g   = rem & 255;            // 8-col group

    const int chain = m >> 2, d = (m >> 1) & 1, l = m & 1;
    const float* src = (l ? (chain ? nW2 : pW2) : (chain ? nW1 : pW1))
                       + (size_t)d * H * H + (size_t)row * H + g * 8;

    float4 f0 = __ldcs((const float4*)src);
    float4 f1 = __ldcs((const float4*)src + 1);

    __half h[8];
    h[0] = __float2half_rn(f0.x); h[1] = __float2half_rn(f0.y);
    h[2] = __float2half_rn(f0.z); h[3] = __float2half_rn(f0.w);
    h[4] = __float2half_rn(f1.x); h[5] = __float2half_rn(f1.y);
    h[6] = __float2half_rn(f1.z); h[7] = __float2half_rn(f1.w);

    const int lc = g >> 2;                // 32-col slice index
    const int co = (g & 3) * 8;
    __half* dst = &g_wh[m][(size_t)lc * H * 32 + (size_t)row * 32 + co];
    *(uint4*)dst = *(const uint4*)h;
}

extern "C" __global__ void __launch_bounds__(NTHREADS, 1)
rnn_kernel(const float* __restrict__ pemb, const float* __restrict__ nemb,
           const float* __restrict__ pb1, const float* __restrict__ pb2,
           const float* __restrict__ nb1, const float* __restrict__ nb2,
           const float* __restrict__ rW) {
    __shared__ float ps[H];              // epilogue reduction scratch (8 KB)
    __shared__ float red[2][32][4][8];   // parity-buffered warp partials (8 KB)

    const int tid   = threadIdx.x;
    const int cta   = blockIdx.x;
    const int chain = cta >> 6;
    const int lc    = cta & (CPC - 1);
    const int c0    = lc * COLS;

    const int jv   = tid & 3;            // col octet 0..3 (8 cols each)
    const int it   = tid >> 2;           // 0..255 row base
    const int warp = tid >> 5, lane = tid & 31;

    const float* B1  = chain ? nb1  : pb1;
    const float* B2  = chain ? nb2  : pb2;
    const float* EMB = chain ? nemb : pemb;

    // seed: own 32 p-columns in a register (tid<32), publish epoch 1
    float pcur = 0.f;
    if (tid < COLS) {
        pcur = __ldcg(EMB + c0 + tid);
        push_pair(&g_sp[chain][c0 + tid], 1u, pcur);
    }

    // prefetch phase-0 weights: 8 row-blocks x 8 cols per thread
    const uint4* wq = (const uint4*)(g_wh[chain * 4] + (size_t)lc * H * 32);
    uint4 w[8];
    #pragma unroll
    for (int k = 0; k < 8; ++k)
        w[k] = wq[(size_t)(it + (k << 8)) * 4 + jv];

    #pragma unroll 1
    for (int ph = 0; ph < NPHASES; ++ph) {
        const int s = ph >> 2, d = (ph >> 1) & 1, l = ph & 1;
        const unsigned ex = (unsigned)(ph >> 1) + 1u;
        const int par = ph & 1;

        // issue all 8 input-word loads up front (full MLP), then
        // verify-epoch + MAC per block; a late producer only delays
        // its own block, overlapping the wait with the other MACs.
        const ull* in = (l ? g_st[chain] : g_sp[chain]) + it;
        ull r[8];
        #pragma unroll
        for (int k = 0; k < 8; ++k) r[k] = ldpair(in + (k << 8));

        float a[8] = {0, 0, 0, 0, 0, 0, 0, 0};
        #pragma unroll
        for (int k = 0; k < 8; ++k) {
            ull v = r[k];
            while ((unsigned)(v >> 32) != ex) {
                __nanosleep(32);
                v = ldpair(in + (k << 8));
            }
            const float pv = __uint_as_float((unsigned)v);
            const __half2* h = (const __half2*)&w[k];
            { float2 f = __half22float2(h[0]); a[0] += pv * f.x; a[1] += pv * f.y; }
            { float2 f = __half22float2(h[1]); a[2] += pv * f.x; a[3] += pv * f.y; }
            { float2 f = __half22float2(h[2]); a[4] += pv * f.x; a[5] += pv * f.y; }
            { float2 f = __half22float2(h[3]); a[6] += pv * f.x; a[7] += pv * f.y; }
        }

        // w[] dead: prefetch next phase's weights NOW (overlaps reduce,
        // publish, and the next poll window -> near-continuous stream)
        if (ph + 1 < NPHASES) {
            const int dn = ((ph + 1) >> 1) & 1, ln = (ph + 1) & 1;
            wq = (const uint4*)(g_wh[chain * 4 + dn * 2 + ln]
                                + (size_t)lc * H * 32);
            #pragma unroll
            for (int k = 0; k < 8; ++k)
                w[k] = wq[(size_t)(it + (k << 8)) * 4 + jv];
        }

        // reduce the 8 it-groups within each warp (lanes differ in bits 2..4)
        #pragma unroll
        for (int m = 4; m <= 16; m <<= 1) {
            #pragma unroll
            for (int j = 0; j < 8; ++j)
                a[j] += __shfl_xor_sync(0xffffffffu, a[j], m);
        }
        if (lane < 4) {
            #pragma unroll
            for (int j = 0; j < 8; ++j) red[par][warp][lane][j] = a[j];
        }
        __syncthreads();   // the ONLY per-phase CTA sync

        // warp 0 finalizes + publishes; other warps race into next polls
        if (tid < COLS) {
            const int j2 = tid >> 3, jj = tid & 7;
            float sum = 0.f;
            #pragma unroll
            for (int wi = 0; wi < 32; ++wi) sum += red[par][wi][j2][jj];

            const int col = c0 + tid;
            if (l == 0) {
                float y = silu(sum + B1[d * H + col]);
                push_pair(&g_st[chain][col], ex, y);
            } else {
                float y = pcur + silu(sum + B2[d * H + col]);
                pcur = y;
                push_pair(&g_sp[chain][col], ex + 1u, y);
                if (d == 1)
                    push_pair(&g_tabp[chain][s][col], (unsigned)s + 1u, y);
            }
        }
    }

    // Epilogue: each CTA projects table rows lc and lc+64 of its chain.
    #pragma unroll
    for (int rr = 0; rr < 2; ++rr) {
        const int r = lc + rr * CPC;
        if (r < STEPS) {
            const ull* row = g_tabp[chain][r];
            const float* rw = rW + chain * H;
            const unsigned ex = (unsigned)r + 1u;
            float v0 = poll_pair(row + tid, ex);
            float v1 = poll_pair(row + tid + 1024, ex);
            float ssum = v0 * rw[tid] + v1 * rw[tid + 1024];
            __syncthreads();
            ps[tid] = ssum;
            __syncthreads();
            #pragma unroll
            for (int sft = 512; sft > 0; sft >>= 1) {
                if (tid < sft) ps[tid] += ps[tid + sft];
                __syncthreads();
            }
            if (tid == 0) g_proj[chain][r] = ps[0];
        }
    }
}

extern "C" __global__ void gather_kernel(const int* __restrict__ x,
                                         const float* __restrict__ rb,
                                         float* __restrict__ out) {
    int b = blockIdx.x * blockDim.x + threadIdx.x;
    if (b < NB) {
        int xp = x[2 * b];
        int xn = x[2 * b + 1];
        float z = g_proj[0][xp] + g_proj[1][xn] + rb[0];
        out[b] = 1.0f / (1.0f + __expf(-z));
    }
}

extern "C" void kernel_launch(void* const* d_in, const int* in_sizes, int n_in,
                              void* d_out, int out_size) {
    (void)in_sizes; (void)n_in; (void)out_size;
    const int*   x    = (const int*)d_in[0];
    const float* pemb = (const float*)d_in[1];
    const float* nemb = (const float*)d_in[2];
    const float* pW1  = (const float*)d_in[3];
    const float* pb1  = (const float*)d_in[4];
    const float* pW2  = (const float*)d_in[5];
    const float* pb2  = (const float*)d_in[6];
    const float* nW1  = (const float*)d_in[7];
    const float* nb1  = (const float*)d_in[8];
    const float* nW2  = (const float*)d_in[9];
    const float* nb2  = (const float*)d_in[10];
    const float* rW   = (const float*)d_in[11];
    const float* rb   = (const float*)d_in[12];
    float* out = (float*)d_out;

    zero_kernel<<<(ZERO_WORDS + 255) / 256, 256>>>();
    convert_kernel<<<8 * 2048 * 256 / 256, 256>>>(pW1, pW2, nW1, nW2);
    rnn_kernel<<<NCTAS, NTHREADS>>>(pemb, nemb, pb1, pb2, nb1, nb2, rW);
    gather_kernel<<<(NB + 255) / 256, 256>>>(x, rb, out);
}

// round 17
// speedup vs baseline: 1.0416x; 1.0416x over previous
#include <cuda_runtime.h>
#include <cuda_fp16.h>

// ============================================================================
// RNN_35244501631277 — GB300 persistent recurrence, round 9 design
// (ninth submit of this design; infra timeouts on the prior eight attempts.)
//
// R8 regressed (2063us): register spills + the real lesson — poll loads queue
// BEHIND the 128KB/phase weight-prefetch LDGs in the SM's single L1tex FIFO,
// inflating the dependency chain to ~1.4us.
// This design: weights stream via TMA (cp.async.bulk -> SMEM ring, 6 x 32KB
// slots, mbarrier completion). The LSU queue now carries only 8 poll loads +
// LDS per thread -> poll observation ~ L2 hit. Slot reuse is made safe
// STRUCTURALLY (2 chunks issued at phase top, 2 after a mid-phase
// __syncthreads; the 6-back chunk is provably consumed at each point) — no
// empty barriers, no deadlock. MAC arithmetic unchanged (same rel_err).
// ============================================================================

#define H          2048
#define STEPS      119
#define NB         16384
#define CPC        64         // CTAs per chain
#define NCTAS      128
#define NTHREADS   1024
#define COLS       32
#define NPHASES    476
#define NBUF       6          // SMEM weight ring slots
#define CHUNK_B    32768      // 512 rows x 32 cols x fp16

// dynamic smem layout
#define MB_OFF     0          // full mbarriers: 6 x 8B
#define RED_OFF    1024       // red[2][32][4][8] floats = 8KB (also epilogue scratch)
#define W_OFF      16384      // weight ring: 6 x 32KB = 192KB
#define SMEM_TOTAL (W_OFF + NBUF * CHUNK_B)   // 212992

typedef unsigned long long ull;

__device__ __half g_wh[8][H * H];        // fp16 weights, CTA-sliced (32 cols)
__device__ ull    g_sp[2][H];            // p-state (epoch|value) words
__device__ ull    g_st[2][H];            // t-state words
__device__ ull    g_tabp[2][STEPS][H];   // step-table words
__device__ float  g_proj[2][STEPS];

#define ZERO_WORDS (2 * H + 2 * H + 2 * STEPS * H)

__device__ __forceinline__ float silu(float x) {
    return x / (1.0f + __expf(-x));
}

__device__ __forceinline__ ull ldpair(const ull* p) {
    ull v;
    asm volatile("ld.global.cg.b64 %0, [%1];" : "=l"(v) : "l"(p));
    return v;
}

__device__ __forceinline__ float poll_pair(const ull* p, unsigned expep) {
    ull v = ldpair(p);
    while ((unsigned)(v >> 32) != expep) {
        __nanosleep(32);
        v = ldpair(p);
    }
    return __uint_as_float((unsigned)v);
}

__device__ __forceinline__ void push_pair(ull* p, unsigned ep, float val) {
    ull v = ((ull)ep << 32) | (ull)__float_as_uint(val);
    asm volatile("st.global.cg.b64 [%0], %1;" :: "l"(p), "l"(v) : "memory");
}

__device__ __forceinline__ void mbar_init(unsigned mb, unsigned cnt) {
    asm volatile("mbarrier.init.shared.b64 [%0], %1;" :: "r"(mb), "r"(cnt)
                 : "memory");
}

__device__ __forceinline__ void mbar_wait(unsigned mb, unsigned par) {
    unsigned done;
    do {
        asm volatile(
            "{\n\t.reg .pred p;\n\t"
            "mbarrier.try_wait.parity.acquire.cta.shared::cta.b64 p, [%1], %2, 0x989680;\n\t"
            "selp.b32 %0, 1, 0, p;\n\t}"
            : "=r"(done) : "r"(mb), "r"(par) : "memory");
    } while (!done);
}

__device__ __forceinline__ void tma_chunk(unsigned dst, const void* src,
                                          unsigned bytes, unsigned mb) {
    asm volatile("mbarrier.arrive.expect_tx.shared.b64 _, [%0], %1;"
                 :: "r"(mb), "r"(bytes) : "memory");
    asm volatile(
        "cp.async.bulk.shared::cta.global.mbarrier::complete_tx::bytes "
        "[%0], [%1], %2, [%3];"
        :: "r"(dst), "l"(src), "r"(bytes), "r"(mb) : "memory");
}

extern "C" __global__ void zero_kernel() {
    int i = blockIdx.x * blockDim.x + threadIdx.x;
    if (i < 2 * H)           ((ull*)g_sp)[i] = 0;
    else if (i < 4 * H)      ((ull*)g_st)[i - 2 * H] = 0;
    else if (i < ZERO_WORDS) ((ull*)g_tabp)[i - 4 * H] = 0;
}

// fp32 -> fp16, CTA-sliced 32-col layout: dst[m][lc*H*32 + row*32 + co]
extern "C" __global__ void convert_kernel(const float* __restrict__ pW1,
                                          const float* __restrict__ pW2,
                                          const float* __restrict__ nW1,
                                          const float* __restrict__ nW2) {
    const int idx = blockIdx.x * blockDim.x + threadIdx.x;
    const int m   = idx >> 19;
    const int rem = idx & ((1 << 19) - 1);
    const int row = rem >> 8;
    const int g   = rem & 255;            // 8-col group

    const int chain = m >> 2, d = (m >> 1) & 1, l = m & 1;
    const float* src = (l ? (chain ? nW2 : pW2) : (chain ? nW1 : pW1))
                       + (size_t)d * H * H + (size_t)row * H + g * 8;

    float4 f0 = __ldcs((const float4*)src);
    float4 f1 = __ldcs((const float4*)src + 1);

    __half h[8];
    h[0] = __float2half_rn(f0.x); h[1] = __float2half_rn(f0.y);
    h[2] = __float2half_rn(f0.z); h[3] = __float2half_rn(f0.w);
    h[4] = __float2half_rn(f1.x); h[5] = __float2half_rn(f1.y);
    h[6] = __float2half_rn(f1.z); h[7] = __float2half_rn(f1.w);

    const int lc = g >> 2;                // 32-col slice index
    const int co = (g & 3) * 8;
    __half* dst = &g_wh[m][(size_t)lc * H * 32 + (size_t)row * 32 + co];
    *(uint4*)dst = *(const uint4*)h;
}

extern "C" __global__ void __launch_bounds__(NTHREADS, 1)
rnn_kernel(const float* __restrict__ pemb, const float* __restrict__ nemb,
           const float* __restrict__ pb1, const float* __restrict__ pb2,
           const float* __restrict__ nb1, const float* __restrict__ nb2,
           const float* __restrict__ rW) {
    extern __shared__ char smem[];
    const unsigned sbase = (unsigned)__cvta_generic_to_shared(smem);
    const unsigned mb0   = sbase + MB_OFF;
    float (*red)[32][4][8] = (float (*)[32][4][8])(smem + RED_OFF);

    const int tid   = threadIdx.x;
    const int cta   = blockIdx.x;
    const int chain = cta >> 6;
    const int lc    = cta & (CPC - 1);
    const int c0    = lc * COLS;

    const int jv   = tid & 3;            // col octet 0..3 (8 cols each)
    const int it   = tid >> 2;           // 0..255 row base
    const int warp = tid >> 5, lane = tid & 31;

    const float* B1  = chain ? nb1  : pb1;
    const float* B2  = chain ? nb2  : pb2;
    const float* EMB = chain ? nemb : pemb;

    // init TMA-completion mbarriers
    if (tid == 0) {
        #pragma unroll
        for (int i = 0; i < NBUF; ++i) mbar_init(mb0 + i * 8, 1u);
        asm volatile("fence.proxy.async.shared::cta;" ::: "memory");
    }
    __syncthreads();

    // producer: issue chunk g (phase g/4, chunk g&3) into slot g%NBUF
    auto issue = [&](int g) {
        const int pn = g >> 2, c = g & 3;
        const int dn = (pn >> 1) & 1, ln = pn & 1;
        const __half* src = g_wh[chain * 4 + dn * 2 + ln]
                            + (size_t)lc * (H * 32) + (size_t)c * (512 * 32);
        const unsigned slot = (unsigned)(g % NBUF);
        tma_chunk(sbase + W_OFF + slot * CHUNK_B, src, CHUNK_B, mb0 + slot * 8);
    };

    // seed: own 32 p-columns in a register (tid<32), publish epoch 1
    float pcur = 0.f;
    if (tid < COLS) {
        pcur = __ldcg(EMB + c0 + tid);
        push_pair(&g_sp[chain][c0 + tid], 1u, pcur);
    }

    // bootstrap: issue phase 0's 4 chunks
    if (tid == 0) { issue(0); issue(1); issue(2); issue(3); }

    int cs = 0, cphase = 0;              // consumer ring cursor (all threads)

    #pragma unroll 1
    for (int ph = 0; ph < NPHASES; ++ph) {
        const int s = ph >> 2, d = (ph >> 1) & 1, l = ph & 1;
        const unsigned ex = (unsigned)(ph >> 1) + 1u;
        const int par = ph & 1;

        // producer: first 2 chunks of next phase (slots provably free:
        // their 6-back chunks were consumed before last phase's end sync)
        if (tid == 0 && ph + 1 < NPHASES) {
            issue(4 * (ph + 1));
            issue(4 * (ph + 1) + 1);
        }

        // issue all 8 input-word polls up front (only LDGs in the LSU queue)
        const ull* in = (l ? g_st[chain] : g_sp[chain]) + it;
        ull r[8];
        #pragma unroll
        for (int k = 0; k < 8; ++k) r[k] = ldpair(in + (k << 8));

        float a[8] = {0, 0, 0, 0, 0, 0, 0, 0};

        #pragma unroll
        for (int c = 0; c < 4; ++c) {
            const unsigned sl = (unsigned)cs;
            mbar_wait(mb0 + sl * 8, (unsigned)cphase);
            const uint4* wb = (const uint4*)(smem + W_OFF + sl * CHUNK_B);

            #pragma unroll
            for (int kk = 0; kk < 2; ++kk) {
                const int k = 2 * c + kk;
                ull v = r[k];
                while ((unsigned)(v >> 32) != ex) {
                    __nanosleep(32);
                    v = ldpair(in + (k << 8));
                }
                const float pv = __uint_as_float((unsigned)v);
                const uint4 wv = wb[(it + (kk << 8)) * 4 + jv];
                const __half2* h = (const __half2*)&wv;
                { float2 f = __half22float2(h[0]); a[0] += pv * f.x; a[1] += pv * f.y; }
                { float2 f = __half22float2(h[1]); a[2] += pv * f.x; a[3] += pv * f.y; }
                { float2 f = __half22float2(h[2]); a[4] += pv * f.x; a[5] += pv * f.y; }
                { float2 f = __half22float2(h[3]); a[6] += pv * f.x; a[7] += pv * f.y; }
            }
            if (++cs == NBUF) { cs = 0; cphase ^= 1; }

            // mid-phase sync: chunks 0,1 consumed by ALL -> their slots
            // (6-back targets of next-phase chunks 2,3) are reusable
            if (c == 1) {
                __syncthreads();
                if (tid == 0 && ph + 1 < NPHASES) {
                    issue(4 * (ph + 1) + 2);
                    issue(4 * (ph + 1) + 3);
                }
            }
        }

        // reduce the 8 it-groups within each warp (lanes differ in bits 2..4)
        #pragma unroll
        for (int m = 4; m <= 16; m <<= 1) {
            #pragma unroll
            for (int j = 0; j < 8; ++j)
                a[j] += __shfl_xor_sync(0xffffffffu, a[j], m);
        }
        if (lane < 4) {
            #pragma unroll
            for (int j = 0; j < 8; ++j) red[par][warp][lane][j] = a[j];
        }
        __syncthreads();

        // warp 0 finalizes + publishes; other warps race into next phase
        if (tid < COLS) {
            const int j2 = tid >> 3, jj = tid & 7;
            float sum = 0.f;
            #pragma unroll
            for (int wi = 0; wi < 32; ++wi) sum += red[par][wi][j2][jj];

            const int col = c0 + tid;
            if (l == 0) {
                float y = silu(sum + B1[d * H + col]);
                push_pair(&g_st[chain][col], ex, y);
            } else {
                float y = pcur + silu(sum + B2[d * H + col]);
                pcur = y;
                push_pair(&g_sp[chain][col], ex + 1u, y);
                if (d == 1)
                    push_pair(&g_tabp[chain][s][col], (unsigned)s + 1u, y);
            }
        }
    }

    // Epilogue: each CTA projects table rows lc and lc+64 of its chain.
    float* sc = (float*)(smem + RED_OFF);
    #pragma unroll
    for (int rr = 0; rr < 2; ++rr) {
        const int r = lc + rr * CPC;
        if (r < STEPS) {
            const ull* row = g_tabp[chain][r];
            const float* rw = rW + chain * H;
            const unsigned exr = (unsigned)r + 1u;
            float v0 = poll_pair(row + tid, exr);
            float v1 = poll_pair(row + tid + 1024, exr);
            float ssum = v0 * rw[tid] + v1 * rw[tid + 1024];
            __syncthreads();
            sc[tid] = ssum;
            __syncthreads();
            #pragma unroll
            for (int sft = 512; sft > 0; sft >>= 1) {
                if (tid < sft) sc[tid] += sc[tid + sft];
                __syncthreads();
            }
            if (tid == 0) g_proj[chain][r] = sc[0];
        }
    }
}

extern "C" __global__ void gather_kernel(const int* __restrict__ x,
                                         const float* __restrict__ rb,
                                         float* __restrict__ out) {
    int b = blockIdx.x * blockDim.x + threadIdx.x;
    if (b < NB) {
        int xp = x[2 * b];
        int xn = x[2 * b + 1];
        float z = g_proj[0][xp] + g_proj[1][xn] + rb[0];
        out[b] = 1.0f / (1.0f + __expf(-z));
    }
}

extern "C" void kernel_launch(void* const* d_in, const int* in_sizes, int n_in,
                              void* d_out, int out_size) {
    (void)in_sizes; (void)n_in; (void)out_size;
    const int*   x    = (const int*)d_in[0];
    const float* pemb = (const float*)d_in[1];
    const float* nemb = (const float*)d_in[2];
    const float* pW1  = (const float*)d_in[3];
    const float* pb1  = (const float*)d_in[4];
    const float* pW2  = (const float*)d_in[5];
    const float* pb2  = (const float*)d_in[6];
    const float* nW1  = (const float*)d_in[7];
    const float* nb1  = (const float*)d_in[8];
    const float* nW2  = (const float*)d_in[9];
    const float* nb2  = (const float*)d_in[10];
    const float* rW   = (const float*)d_in[11];
    const float* rb   = (const float*)d_in[12];
    float* out = (float*)d_out;

    // unconditional every call (no static guards — harness rule); idempotent
    cudaFuncSetAttribute(rnn_kernel,
                         cudaFuncAttributeMaxDynamicSharedMemorySize,
                         SMEM_TOTAL);

    zero_kernel<<<(ZERO_WORDS + 255) / 256, 256>>>();
    convert_kernel<<<8 * 2048 * 256 / 256, 256>>>(pW1, pW2, nW1, nW2);
    rnn_kernel<<<NCTAS, NTHREADS, SMEM_TOTAL>>>(pemb, nemb, pb1, pb2,
                                                nb1, nb2, rW);
    gather_kernel<<<(NB + 255) / 256, 256>>>(x, rb, out);
}